// round 5
// baseline (speedup 1.0000x reference)
#include <cuda_runtime.h>

// y[4096] = x[1,5504] @ W[4096, act_idx[cluster]]^T + bias
// Fully fused, all-148-SM single wave:
//   grid=148, block=1024 (32 warps). Warp w of block b computes row w*148+b
//   (blocks get 27-28 rows; perfectly balanced). Each block builds the
//   densified xs[11008] in smem, then streams its W rows with float4 loads.
//   First W loads are issued BEFORE the prologue to hide it under DRAM latency.

#define D_OUT 4096
#define D_IN 11008
#define REMAINED 5504
#define THREADS 1024
#define NBLOCKS 148

__global__ __launch_bounds__(THREADS, 1) void fused_gemv_kernel(
    const float* __restrict__ x,
    const float* __restrict__ weight,
    const float* __restrict__ bias,
    const int*   __restrict__ act_idx,
    const int*   __restrict__ cluster,
    float*       __restrict__ out)
{
    __shared__ float sxs[D_IN];  // 44032 bytes

    const int warp = threadIdx.x >> 5;
    const int lane = threadIdx.x & 31;
    const int row  = warp * NBLOCKS + blockIdx.x;   // 0..4735; guard at 4096
    const bool active = row < D_OUT;

    const float4* __restrict__ w4 =
        reinterpret_cast<const float4*>(weight + (size_t)row * D_IN);

    // Prefetch first pair of W elements before the prologue (hides the
    // zero+scatter phase under the first DRAM round-trip).
    float4 p0, p1;
    if (active) {
        p0 = __ldcs(w4 + lane);
        p1 = __ldcs(w4 + lane + 32);
    }

    // 1) zero smem
    float4* sxs4 = reinterpret_cast<float4*>(sxs);
    #pragma unroll
    for (int i = threadIdx.x; i < D_IN / 4; i += THREADS)
        sxs4[i] = make_float4(0.f, 0.f, 0.f, 0.f);
    __syncthreads();

    // 2) gather x + idx (L2-resident after first readers), scatter into smem
    const int cl = *cluster;
    const int* idx_row = act_idx + cl * REMAINED;
    #pragma unroll
    for (int i = threadIdx.x; i < REMAINED; i += THREADS) {
        int   c = __ldg(idx_row + i);
        float v = __ldg(x + i);
        atomicAdd(&sxs[c], v);
    }
    __syncthreads();

    // 3) dense GEMV: one warp per row
    if (active) {
        const float4* sx4 = reinterpret_cast<const float4*>(sxs);

        // consume prefetched pair (peeled first iteration)
        float4 b0 = sx4[lane];
        float4 b1 = sx4[lane + 32];
        float acc0 = p0.x * b0.x, acc1 = p1.x * b1.x;
        acc0 = fmaf(p0.y, b0.y, acc0);
        acc0 = fmaf(p0.z, b0.z, acc0);
        acc0 = fmaf(p0.w, b0.w, acc0);
        acc1 = fmaf(p1.y, b1.y, acc1);
        acc1 = fmaf(p1.z, b1.z, acc1);
        acc1 = fmaf(p1.w, b1.w, acc1);

        // remaining 42 pair-iterations: 2752 float4 / 64-stride, first peeled
        static_assert((D_IN / 4) % 64 == 0, "row must split into pair-strides");
        #pragma unroll 2
        for (int i = lane + 64; i < D_IN / 4; i += 64) {
            float4 a0 = __ldcs(w4 + i);
            float4 a1 = __ldcs(w4 + i + 32);
            float4 c0 = sx4[i];
            float4 c1 = sx4[i + 32];
            acc0 = fmaf(a0.x, c0.x, acc0);
            acc0 = fmaf(a0.y, c0.y, acc0);
            acc0 = fmaf(a0.z, c0.z, acc0);
            acc0 = fmaf(a0.w, c0.w, acc0);
            acc1 = fmaf(a1.x, c1.x, acc1);
            acc1 = fmaf(a1.y, c1.y, acc1);
            acc1 = fmaf(a1.z, c1.z, acc1);
            acc1 = fmaf(a1.w, c1.w, acc1);
        }

        float acc = acc0 + acc1;
        #pragma unroll
        for (int off = 16; off > 0; off >>= 1)
            acc += __shfl_xor_sync(0xffffffffu, acc, off);

        if (lane == 0)
            out[row] = acc + bias[row];
    }
}

extern "C" void kernel_launch(void* const* d_in, const int* in_sizes, int n_in,
                              void* d_out, int out_size) {
    const float* x       = (const float*)d_in[0];   // (1, 5504)
    const float* weight  = (const float*)d_in[1];   // (4096, 11008)
    const float* bias    = (const float*)d_in[2];   // (4096,)
    const int*   act_idx = (const int*)d_in[3];     // (64, 5504) int32 (jax x64 off)
    const int*   cluster = (const int*)d_in[4];     // scalar int32
    float*       out     = (float*)d_out;           // (1, 4096)

    fused_gemv_kernel<<<NBLOCKS, THREADS>>>(x, weight, bias, act_idx, cluster, out);
}